// round 2
// baseline (speedup 1.0000x reference)
#include <cuda_runtime.h>
#include <math_constants.h>

#define NN 50000
#define NE 800000
#define FIN 128
#define DD 64
#define HH 4
#define HD 256   // H*D
#define EDIM 20

#define SCHUNK 200
#define NSB 250   // NSB * SCHUNK == NN

// ---------------- scratch (device globals) ----------------
__device__ float g_h[NN * DD];          // 12.8 MB node features
__device__ float g_xl[NN * HD];         // 51.2 MB
__device__ float g_xr[NN * HD];         // 51.2 MB
__device__ float g_ecsr[NE * EDIM];     // 64 MB edge embeddings in CSR order
__device__ int   g_cnt[NN];
__device__ int   g_cur[NN];
__device__ int   g_rowptr[NN + 1];
__device__ int   g_bsum[NSB];
__device__ int   g_csr_src[NE];
__device__ int   g_csr_eid[NE];

// ---------------- h0 = relu(x @ f_W + f_b) ----------------
__global__ void k_h0(const float* __restrict__ x, const float* __restrict__ fW,
                     const float* __restrict__ fb) {
    __shared__ float Ws[FIN * DD];
    __shared__ float xs[4][FIN];
    int t = threadIdx.x;
    for (int i = t; i < FIN * DD; i += 256) Ws[i] = fW[i];
    int n0 = blockIdx.x * 4;
    for (int i = t; i < 4 * FIN; i += 256) {
        int r = i / FIN, k = i % FIN;
        int n = n0 + r;
        xs[r][k] = (n < NN) ? x[n * FIN + k] : 0.f;
    }
    __syncthreads();
    int r = t >> 6, d = t & 63;
    int n = n0 + r;
    if (n < NN) {
        float acc = fb[d];
#pragma unroll 8
        for (int k = 0; k < FIN; k++) acc = fmaf(xs[r][k], Ws[k * DD + d], acc);
        g_h[n * DD + d] = fmaxf(acc, 0.f);
    }
}

// ---------------- CSR build ----------------
__global__ void k_zero() {
    int i = blockIdx.x * blockDim.x + threadIdx.x;
    if (i < NN) { g_cnt[i] = 0; g_cur[i] = 0; }
}

__global__ void k_hist(const int* __restrict__ ei) {
    int e = blockIdx.x * blockDim.x + threadIdx.x;
    if (e < NE) atomicAdd(&g_cnt[ei[NE + e]], 1);
}

__global__ void k_scan_a() {
    __shared__ int s[256];
    int b = blockIdx.x, t = threadIdx.x;
    s[t] = (t < SCHUNK) ? g_cnt[b * SCHUNK + t] : 0;
    __syncthreads();
    for (int off = 128; off; off >>= 1) {
        if (t < off) s[t] += s[t + off];
        __syncthreads();
    }
    if (t == 0) g_bsum[b] = s[0];
}

__global__ void k_scan_b() {
    __shared__ int s[NSB];
    int t = threadIdx.x;
    for (int i = t; i < NSB; i += blockDim.x) s[i] = g_bsum[i];
    __syncthreads();
    if (t == 0) {
        int run = 0;
        for (int i = 0; i < NSB; i++) { int v = s[i]; g_bsum[i] = run; run += v; }
        g_rowptr[NN] = NE;
    }
}

__global__ void k_scan_c() {
    __shared__ int s[256];
    __shared__ int cnt_s[256];
    int b = blockIdx.x, t = threadIdx.x;
    int c = (t < SCHUNK) ? g_cnt[b * SCHUNK + t] : 0;
    cnt_s[t] = c;
    s[t] = c;
    __syncthreads();
    // inclusive Hillis-Steele
    for (int off = 1; off < 256; off <<= 1) {
        int v = (t >= off) ? s[t - off] : 0;
        __syncthreads();
        s[t] += v;
        __syncthreads();
    }
    if (t < SCHUNK) {
        int base = g_bsum[b];
        g_rowptr[b * SCHUNK + t] = base + s[t] - cnt_s[t];  // exclusive
    }
}

__global__ void k_scatter(const int* __restrict__ ei) {
    int e = blockIdx.x * blockDim.x + threadIdx.x;
    if (e >= NE) return;
    int dst = ei[NE + e];
    int pos = g_rowptr[dst] + atomicAdd(&g_cur[dst], 1);
    g_csr_src[pos] = ei[e];
    g_csr_eid[pos] = e;
}

// ---------------- e = relu(edge_attr @ fe_W + fe_b) directly into CSR order ----
__global__ void k_eemb_csr(const float* __restrict__ ea, const float* __restrict__ feW,
                           const float* __restrict__ feb) {
    int pos = blockIdx.x * blockDim.x + threadIdx.x;
    if (pos >= NE) return;
    int eid = g_csr_eid[pos];
    float a0 = __ldg(&ea[eid * 2]), a1 = __ldg(&ea[eid * 2 + 1]);
#pragma unroll
    for (int j = 0; j < EDIM; j++) {
        float v = fmaf(a0, __ldg(&feW[j]), fmaf(a1, __ldg(&feW[EDIM + j]), __ldg(&feb[j])));
        g_ecsr[pos * EDIM + j] = fmaxf(v, 0.f);
    }
}

// ---------------- xl = h@Wl+bl, xr = h@Wr+br ----------------
__global__ void k_lin(const float* __restrict__ Wl, const float* __restrict__ bl,
                      const float* __restrict__ Wr, const float* __restrict__ br) {
    __shared__ float4 Ws[DD][32];
    __shared__ float  hs[32][DD];
    int t = threadIdx.y * 32 + threadIdx.x;
    int tile_c = blockIdx.y * 128;
    const float* W  = (tile_c < HD) ? Wl : Wr;
    const float* bb = (tile_c < HD) ? bl : br;
    int cb = tile_c & (HD - 1);
    for (int i = t; i < DD * 32; i += 256) {
        int k = i / 32, q = i % 32;
        Ws[k][q] = ((const float4*)(W + k * HD + cb))[q];
    }
    int n0 = blockIdx.x * 32;
    for (int i = t; i < 32 * DD; i += 256) {
        int r = i / DD, k = i % DD;
        int n = n0 + r;
        hs[r][k] = (n < NN) ? g_h[n * DD + k] : 0.f;
    }
    __syncthreads();
    int lane = threadIdx.x, ty = threadIdx.y;
    float4 bv = ((const float4*)(bb + cb))[lane];
    float4 acc[4];
#pragma unroll
    for (int q = 0; q < 4; q++) acc[q] = bv;
#pragma unroll 16
    for (int k = 0; k < DD; k++) {
        float4 w = Ws[k][lane];
#pragma unroll
        for (int q = 0; q < 4; q++) {
            float hv = hs[ty * 4 + q][k];
            acc[q].x = fmaf(hv, w.x, acc[q].x);
            acc[q].y = fmaf(hv, w.y, acc[q].y);
            acc[q].z = fmaf(hv, w.z, acc[q].z);
            acc[q].w = fmaf(hv, w.w, acc[q].w);
        }
    }
    float* outp = (tile_c < HD) ? g_xl : g_xr;
#pragma unroll
    for (int q = 0; q < 4; q++) {
        int n = n0 + ty * 4 + q;
        if (n < NN) ((float4*)(outp + n * HD + cb))[lane] = acc[q];
    }
}

// ---------------- fused: score + online softmax + aggregate + head-mean ------
// one warp per dst node; lane handles dims j = lane*8 .. lane*8+7 (head = lane>>3)
__global__ void k_fused(const float* __restrict__ We, const float* __restrict__ att,
                        const float* __restrict__ bias, float* __restrict__ dout,
                        int writeOut) {
    __shared__ float4 Wsh[EDIM * 64];   // 20 KB: We[k][j] as float4
    int t = threadIdx.x;
    for (int i = t; i < EDIM * 64; i += 256) Wsh[i] = ((const float4*)We)[i];
    __syncthreads();

    int wid = t >> 5, lane = t & 31;
    int n = blockIdx.x * 8 + wid;
    if (n >= NN) return;

    int beg = g_rowptr[n], end = g_rowptr[n + 1];

    const float4* xr4 = (const float4*)(g_xr + (size_t)n * HD);
    float4 r0 = xr4[lane * 2], r1 = xr4[lane * 2 + 1];
    float4 av0 = __ldg(&((const float4*)att)[lane * 2]);
    float4 av1 = __ldg(&((const float4*)att)[lane * 2 + 1]);

    float m_run = -CUDART_INF_F, s_run = 0.f;
    float4 acc0 = make_float4(0, 0, 0, 0), acc1 = make_float4(0, 0, 0, 0);

    for (int p = beg; p < end; p++) {
        int src = __ldg(&g_csr_src[p]);
        float ev = (lane < EDIM) ? g_ecsr[p * EDIM + lane] : 0.f;
        const float4* xl4 = (const float4*)(g_xl + (size_t)src * HD);
        float4 a = xl4[lane * 2], b = xl4[lane * 2 + 1];

        float4 e0 = make_float4(0, 0, 0, 0), e1 = make_float4(0, 0, 0, 0);
#pragma unroll
        for (int k = 0; k < EDIM; k++) {
            float ek = __shfl_sync(0xffffffffu, ev, k);
            float4 w0 = Wsh[k * 64 + lane * 2];
            float4 w1 = Wsh[k * 64 + lane * 2 + 1];
            e0.x = fmaf(ek, w0.x, e0.x); e0.y = fmaf(ek, w0.y, e0.y);
            e0.z = fmaf(ek, w0.z, e0.z); e0.w = fmaf(ek, w0.w, e0.w);
            e1.x = fmaf(ek, w1.x, e1.x); e1.y = fmaf(ek, w1.y, e1.y);
            e1.z = fmaf(ek, w1.z, e1.z); e1.w = fmaf(ek, w1.w, e1.w);
        }
        // leaky-relu(xl + xr + ee) dot att
        float s = 0.f;
        {
            float m;
            m = a.x + r0.x + e0.x; m = m > 0.f ? m : 0.2f * m; s = fmaf(av0.x, m, s);
            m = a.y + r0.y + e0.y; m = m > 0.f ? m : 0.2f * m; s = fmaf(av0.y, m, s);
            m = a.z + r0.z + e0.z; m = m > 0.f ? m : 0.2f * m; s = fmaf(av0.z, m, s);
            m = a.w + r0.w + e0.w; m = m > 0.f ? m : 0.2f * m; s = fmaf(av0.w, m, s);
            m = b.x + r1.x + e1.x; m = m > 0.f ? m : 0.2f * m; s = fmaf(av1.x, m, s);
            m = b.y + r1.y + e1.y; m = m > 0.f ? m : 0.2f * m; s = fmaf(av1.y, m, s);
            m = b.z + r1.z + e1.z; m = m > 0.f ? m : 0.2f * m; s = fmaf(av1.z, m, s);
            m = b.w + r1.w + e1.w; m = m > 0.f ? m : 0.2f * m; s = fmaf(av1.w, m, s);
        }
        // reduce within the 8-lane head group
        s += __shfl_xor_sync(0xffffffffu, s, 1);
        s += __shfl_xor_sync(0xffffffffu, s, 2);
        s += __shfl_xor_sync(0xffffffffu, s, 4);

        // online softmax update (per head, replicated over the 8 lanes)
        float nm   = fmaxf(m_run, s);
        float corr = __expf(m_run - nm);
        float w    = __expf(s - nm);
        m_run = nm;
        s_run = fmaf(s_run, corr, w);
        acc0.x = fmaf(acc0.x, corr, w * a.x); acc0.y = fmaf(acc0.y, corr, w * a.y);
        acc0.z = fmaf(acc0.z, corr, w * a.z); acc0.w = fmaf(acc0.w, corr, w * a.w);
        acc1.x = fmaf(acc1.x, corr, w * b.x); acc1.y = fmaf(acc1.y, corr, w * b.y);
        acc1.z = fmaf(acc1.z, corr, w * b.z); acc1.w = fmaf(acc1.w, corr, w * b.w);
    }

    float inv = (end > beg) ? 1.f / s_run : 0.f;
    float v[8];
    v[0] = acc0.x * inv; v[1] = acc0.y * inv; v[2] = acc0.z * inv; v[3] = acc0.w * inv;
    v[4] = acc1.x * inv; v[5] = acc1.y * inv; v[6] = acc1.z * inv; v[7] = acc1.w * inv;
    // head-mean butterfly (combine lanes differing in head index bits 3,4 of lane)
#pragma unroll
    for (int u = 0; u < 8; u++) {
        v[u] += __shfl_xor_sync(0xffffffffu, v[u], 8);
        v[u] += __shfl_xor_sync(0xffffffffu, v[u], 16);
    }
    if (lane < 8) {
        float4 b0 = __ldg(&((const float4*)bias)[lane * 2]);
        float4 b1 = __ldg(&((const float4*)bias)[lane * 2 + 1]);
        float4 o0, o1;
        o0.x = fmaxf(0.25f * v[0] + b0.x, 0.f);
        o0.y = fmaxf(0.25f * v[1] + b0.y, 0.f);
        o0.z = fmaxf(0.25f * v[2] + b0.z, 0.f);
        o0.w = fmaxf(0.25f * v[3] + b0.w, 0.f);
        o1.x = fmaxf(0.25f * v[4] + b1.x, 0.f);
        o1.y = fmaxf(0.25f * v[5] + b1.y, 0.f);
        o1.z = fmaxf(0.25f * v[6] + b1.z, 0.f);
        o1.w = fmaxf(0.25f * v[7] + b1.w, 0.f);
        float* outp = writeOut ? dout : g_h;
        ((float4*)(outp + n * DD))[lane * 2]     = o0;
        ((float4*)(outp + n * DD))[lane * 2 + 1] = o1;
    }
}

// ---------------- launch ----------------
extern "C" void kernel_launch(void* const* d_in, const int* in_sizes, int n_in,
                              void* d_out, int out_size) {
    const float* x   = (const float*)d_in[0];
    const float* ea  = (const float*)d_in[1];
    const int*   ei  = (const int*)  d_in[2];
    const float* fW  = (const float*)d_in[3];
    const float* fb  = (const float*)d_in[4];
    const float* feW = (const float*)d_in[5];
    const float* feb = (const float*)d_in[6];
    const float* Wl  = (const float*)d_in[7];
    const float* bl  = (const float*)d_in[8];
    const float* Wr  = (const float*)d_in[9];
    const float* br  = (const float*)d_in[10];
    const float* We  = (const float*)d_in[11];
    const float* att = (const float*)d_in[12];
    const float* bias= (const float*)d_in[13];

    // prologue
    k_h0<<<NN / 4, 256>>>(x, fW, fb);
    k_zero<<<(NN + 255) / 256, 256>>>();
    k_hist<<<(NE + 255) / 256, 256>>>(ei);
    k_scan_a<<<NSB, 256>>>();
    k_scan_b<<<1, 256>>>();
    k_scan_c<<<NSB, 256>>>();
    k_scatter<<<(NE + 255) / 256, 256>>>(ei);
    k_eemb_csr<<<(NE + 255) / 256, 256>>>(ea, feW, feb);

    for (int l = 0; l < 3; l++) {
        k_lin<<<dim3((NN + 31) / 32, 4), dim3(32, 8)>>>(Wl, bl, Wr, br);
        k_fused<<<(NN + 7) / 8, 256>>>(We, att, bias, (float*)d_out, l == 2 ? 1 : 0);
    }
}

// round 3
// speedup vs baseline: 2.0906x; 2.0906x over previous
#include <cuda_runtime.h>
#include <math_constants.h>

#define NN 50000
#define NE 800000
#define FIN 128
#define DD 64
#define HH 4
#define HD 256   // H*D
#define EDIM 20

#define SCHUNK 200
#define NSB 250   // NSB * SCHUNK == NN

// ---------------- scratch (device globals) ----------------
__device__ float g_h[NN * DD];          // 12.8 MB node features
__device__ float g_xl[NN * HD];         // 51.2 MB
__device__ float g_xr[NN * HD];         // 51.2 MB
__device__ float g_ecsr[NE * EDIM];     // 64 MB edge embeddings (CSR order)
__device__ float g_eecsr[NE * HD];      // 819 MB ee = e@We (CSR order, layer-invariant)
__device__ int   g_cnt[NN];
__device__ int   g_cur[NN];
__device__ int   g_rowptr[NN + 1];
__device__ int   g_bsum[NSB];
__device__ int   g_csr_src[NE];
__device__ int   g_csr_eid[NE];

// ---------------- h0 = relu(x @ f_W + f_b) ----------------
__global__ void k_h0(const float* __restrict__ x, const float* __restrict__ fW,
                     const float* __restrict__ fb) {
    __shared__ float Ws[FIN * DD];
    __shared__ float xs[4][FIN];
    int t = threadIdx.x;
    for (int i = t; i < FIN * DD; i += 256) Ws[i] = fW[i];
    int n0 = blockIdx.x * 4;
    for (int i = t; i < 4 * FIN; i += 256) {
        int r = i / FIN, k = i % FIN;
        int n = n0 + r;
        xs[r][k] = (n < NN) ? x[n * FIN + k] : 0.f;
    }
    __syncthreads();
    int r = t >> 6, d = t & 63;
    int n = n0 + r;
    if (n < NN) {
        float acc = fb[d];
#pragma unroll 8
        for (int k = 0; k < FIN; k++) acc = fmaf(xs[r][k], Ws[k * DD + d], acc);
        g_h[n * DD + d] = fmaxf(acc, 0.f);
    }
}

// ---------------- CSR build ----------------
__global__ void k_zero() {
    int i = blockIdx.x * blockDim.x + threadIdx.x;
    if (i < NN) { g_cnt[i] = 0; g_cur[i] = 0; }
}

__global__ void k_hist(const int* __restrict__ ei) {
    int e = blockIdx.x * blockDim.x + threadIdx.x;
    if (e < NE) atomicAdd(&g_cnt[ei[NE + e]], 1);
}

__global__ void k_scan_a() {
    __shared__ int s[256];
    int b = blockIdx.x, t = threadIdx.x;
    s[t] = (t < SCHUNK) ? g_cnt[b * SCHUNK + t] : 0;
    __syncthreads();
    for (int off = 128; off; off >>= 1) {
        if (t < off) s[t] += s[t + off];
        __syncthreads();
    }
    if (t == 0) g_bsum[b] = s[0];
}

__global__ void k_scan_b() {
    __shared__ int s[NSB];
    int t = threadIdx.x;
    for (int i = t; i < NSB; i += blockDim.x) s[i] = g_bsum[i];
    __syncthreads();
    if (t == 0) {
        int run = 0;
        for (int i = 0; i < NSB; i++) { int v = s[i]; g_bsum[i] = run; run += v; }
        g_rowptr[NN] = NE;
    }
}

__global__ void k_scan_c() {
    __shared__ int s[256];
    __shared__ int cnt_s[256];
    int b = blockIdx.x, t = threadIdx.x;
    int c = (t < SCHUNK) ? g_cnt[b * SCHUNK + t] : 0;
    cnt_s[t] = c;
    s[t] = c;
    __syncthreads();
    for (int off = 1; off < 256; off <<= 1) {
        int v = (t >= off) ? s[t - off] : 0;
        __syncthreads();
        s[t] += v;
        __syncthreads();
    }
    if (t < SCHUNK) {
        int base = g_bsum[b];
        g_rowptr[b * SCHUNK + t] = base + s[t] - cnt_s[t];  // exclusive
    }
}

__global__ void k_scatter(const int* __restrict__ ei) {
    int e = blockIdx.x * blockDim.x + threadIdx.x;
    if (e >= NE) return;
    int dst = ei[NE + e];
    int pos = g_rowptr[dst] + atomicAdd(&g_cur[dst], 1);
    g_csr_src[pos] = ei[e];
    g_csr_eid[pos] = e;
}

// ---------------- e = relu(edge_attr @ fe_W + fe_b) in CSR order ----------
__global__ void k_eemb_csr(const float* __restrict__ ea, const float* __restrict__ feW,
                           const float* __restrict__ feb) {
    int pos = blockIdx.x * blockDim.x + threadIdx.x;
    if (pos >= NE) return;
    int eid = g_csr_eid[pos];
    float a0 = __ldg(&ea[eid * 2]), a1 = __ldg(&ea[eid * 2 + 1]);
#pragma unroll
    for (int j = 0; j < EDIM; j++) {
        float v = fmaf(a0, __ldg(&feW[j]), fmaf(a1, __ldg(&feW[EDIM + j]), __ldg(&feb[j])));
        g_ecsr[pos * EDIM + j] = fmaxf(v, 0.f);
    }
}

// ---------------- ee = e @ We (once, CSR order) ----------------
// block (32,8): lane -> 8 cols (2 float4), ty -> 4 edges. 32 edges x 256 cols / block.
__global__ void k_ee(const float* __restrict__ We) {
    __shared__ float4 Ws4[EDIM][64];   // 20 KB
    __shared__ float  es[32][EDIM + 1];
    int t = threadIdx.y * 32 + threadIdx.x;
    for (int i = t; i < EDIM * 64; i += 256)
        Ws4[i / 64][i % 64] = ((const float4*)We)[i];
    int e0 = blockIdx.x * 32;
    for (int i = t; i < 32 * EDIM; i += 256) {
        int r = i / EDIM, k = i % EDIM;
        es[r][k] = g_ecsr[(e0 + r) * EDIM + k];
    }
    __syncthreads();
    int lane = threadIdx.x, ty = threadIdx.y;
    float4 a0[4], a1[4];
#pragma unroll
    for (int r = 0; r < 4; r++) { a0[r] = make_float4(0,0,0,0); a1[r] = make_float4(0,0,0,0); }
#pragma unroll
    for (int k = 0; k < EDIM; k++) {
        float4 w0 = Ws4[k][lane * 2];
        float4 w1 = Ws4[k][lane * 2 + 1];
#pragma unroll
        for (int r = 0; r < 4; r++) {
            float ev = es[ty * 4 + r][k];
            a0[r].x = fmaf(ev, w0.x, a0[r].x); a0[r].y = fmaf(ev, w0.y, a0[r].y);
            a0[r].z = fmaf(ev, w0.z, a0[r].z); a0[r].w = fmaf(ev, w0.w, a0[r].w);
            a1[r].x = fmaf(ev, w1.x, a1[r].x); a1[r].y = fmaf(ev, w1.y, a1[r].y);
            a1[r].z = fmaf(ev, w1.z, a1[r].z); a1[r].w = fmaf(ev, w1.w, a1[r].w);
        }
    }
#pragma unroll
    for (int r = 0; r < 4; r++) {
        int e = e0 + ty * 4 + r;
        float4* dst = (float4*)(g_eecsr + (size_t)e * HD);
        dst[lane * 2]     = a0[r];
        dst[lane * 2 + 1] = a1[r];
    }
}

// ---------------- xl = h@Wl+bl, xr = h@Wr+br ----------------
__global__ void k_lin(const float* __restrict__ Wl, const float* __restrict__ bl,
                      const float* __restrict__ Wr, const float* __restrict__ br) {
    __shared__ float4 Ws[DD][32];
    __shared__ float  hs[32][DD];
    int t = threadIdx.y * 32 + threadIdx.x;
    int tile_c = blockIdx.y * 128;
    const float* W  = (tile_c < HD) ? Wl : Wr;
    const float* bb = (tile_c < HD) ? bl : br;
    int cb = tile_c & (HD - 1);
    for (int i = t; i < DD * 32; i += 256) {
        int k = i / 32, q = i % 32;
        Ws[k][q] = ((const float4*)(W + k * HD + cb))[q];
    }
    int n0 = blockIdx.x * 32;
    for (int i = t; i < 32 * DD; i += 256) {
        int r = i / DD, k = i % DD;
        int n = n0 + r;
        hs[r][k] = (n < NN) ? g_h[n * DD + k] : 0.f;
    }
    __syncthreads();
    int lane = threadIdx.x, ty = threadIdx.y;
    float4 bv = ((const float4*)(bb + cb))[lane];
    float4 acc[4];
#pragma unroll
    for (int q = 0; q < 4; q++) acc[q] = bv;
#pragma unroll 16
    for (int k = 0; k < DD; k++) {
        float4 w = Ws[k][lane];
#pragma unroll
        for (int q = 0; q < 4; q++) {
            float hv = hs[ty * 4 + q][k];
            acc[q].x = fmaf(hv, w.x, acc[q].x);
            acc[q].y = fmaf(hv, w.y, acc[q].y);
            acc[q].z = fmaf(hv, w.z, acc[q].z);
            acc[q].w = fmaf(hv, w.w, acc[q].w);
        }
    }
    float* outp = (tile_c < HD) ? g_xl : g_xr;
#pragma unroll
    for (int q = 0; q < 4; q++) {
        int n = n0 + ty * 4 + q;
        if (n < NN) ((float4*)(outp + n * HD + cb))[lane] = acc[q];
    }
}

// ---------------- fused: score + online softmax + aggregate + head-mean ------
// one warp per dst node; lane handles dims j = lane*8 .. lane*8+7 (head = lane>>3)
__global__ void __launch_bounds__(256) k_fused(const float* __restrict__ att,
                        const float* __restrict__ bias, float* __restrict__ dout,
                        int writeOut) {
    int t = threadIdx.x;
    int wid = t >> 5, lane = t & 31;
    int n = blockIdx.x * 8 + wid;
    if (n >= NN) return;

    int beg = g_rowptr[n], end = g_rowptr[n + 1];

    const float4* xr4 = (const float4*)(g_xr + (size_t)n * HD);
    float4 r0 = xr4[lane * 2], r1 = xr4[lane * 2 + 1];
    float4 av0 = __ldg(&((const float4*)att)[lane * 2]);
    float4 av1 = __ldg(&((const float4*)att)[lane * 2 + 1]);

    float m_run = -CUDART_INF_F, s_run = 0.f;
    float4 acc0 = make_float4(0, 0, 0, 0), acc1 = make_float4(0, 0, 0, 0);

    // software-pipelined: loads for p, compute on previously loaded values
    float4 a, b, f0, f1;
    if (beg < end) {
        int src = __ldg(&g_csr_src[beg]);
        const float4* xl4 = (const float4*)(g_xl + (size_t)src * HD);
        a = __ldg(&xl4[lane * 2]);
        b = __ldg(&xl4[lane * 2 + 1]);
        const float4* ee4 = (const float4*)(g_eecsr + (size_t)beg * HD);
        f0 = __ldcs(&ee4[lane * 2]);
        f1 = __ldcs(&ee4[lane * 2 + 1]);
    }

    for (int p = beg; p < end; p++) {
        float4 ca = a, cb = b, e0 = f0, e1 = f1;
        if (p + 1 < end) {
            int src = __ldg(&g_csr_src[p + 1]);
            const float4* xl4 = (const float4*)(g_xl + (size_t)src * HD);
            a = __ldg(&xl4[lane * 2]);
            b = __ldg(&xl4[lane * 2 + 1]);
            const float4* ee4 = (const float4*)(g_eecsr + (size_t)(p + 1) * HD);
            f0 = __ldcs(&ee4[lane * 2]);
            f1 = __ldcs(&ee4[lane * 2 + 1]);
        }
        // leaky_relu(xl + xr + ee) dot att
        float s = 0.f;
        {
            float m;
            m = ca.x + r0.x + e0.x; m = m > 0.f ? m : 0.2f * m; s = fmaf(av0.x, m, s);
            m = ca.y + r0.y + e0.y; m = m > 0.f ? m : 0.2f * m; s = fmaf(av0.y, m, s);
            m = ca.z + r0.z + e0.z; m = m > 0.f ? m : 0.2f * m; s = fmaf(av0.z, m, s);
            m = ca.w + r0.w + e0.w; m = m > 0.f ? m : 0.2f * m; s = fmaf(av0.w, m, s);
            m = cb.x + r1.x + e1.x; m = m > 0.f ? m : 0.2f * m; s = fmaf(av1.x, m, s);
            m = cb.y + r1.y + e1.y; m = m > 0.f ? m : 0.2f * m; s = fmaf(av1.y, m, s);
            m = cb.z + r1.z + e1.z; m = m > 0.f ? m : 0.2f * m; s = fmaf(av1.z, m, s);
            m = cb.w + r1.w + e1.w; m = m > 0.f ? m : 0.2f * m; s = fmaf(av1.w, m, s);
        }
        // reduce within the 8-lane head group
        s += __shfl_xor_sync(0xffffffffu, s, 1);
        s += __shfl_xor_sync(0xffffffffu, s, 2);
        s += __shfl_xor_sync(0xffffffffu, s, 4);

        // online softmax update (replicated across the 8 lanes of the head)
        float nm   = fmaxf(m_run, s);
        float corr = __expf(m_run - nm);
        float w    = __expf(s - nm);
        m_run = nm;
        s_run = fmaf(s_run, corr, w);
        acc0.x = fmaf(acc0.x, corr, w * ca.x); acc0.y = fmaf(acc0.y, corr, w * ca.y);
        acc0.z = fmaf(acc0.z, corr, w * ca.z); acc0.w = fmaf(acc0.w, corr, w * ca.w);
        acc1.x = fmaf(acc1.x, corr, w * cb.x); acc1.y = fmaf(acc1.y, corr, w * cb.y);
        acc1.z = fmaf(acc1.z, corr, w * cb.z); acc1.w = fmaf(acc1.w, corr, w * cb.w);
    }

    float inv = (end > beg) ? 1.f / s_run : 0.f;
    float v[8];
    v[0] = acc0.x * inv; v[1] = acc0.y * inv; v[2] = acc0.z * inv; v[3] = acc0.w * inv;
    v[4] = acc1.x * inv; v[5] = acc1.y * inv; v[6] = acc1.z * inv; v[7] = acc1.w * inv;
    // head-mean butterfly (head index = lane bits 3,4)
#pragma unroll
    for (int u = 0; u < 8; u++) {
        v[u] += __shfl_xor_sync(0xffffffffu, v[u], 8);
        v[u] += __shfl_xor_sync(0xffffffffu, v[u], 16);
    }
    if (lane < 8) {
        float4 b0 = __ldg(&((const float4*)bias)[lane * 2]);
        float4 b1 = __ldg(&((const float4*)bias)[lane * 2 + 1]);
        float4 o0, o1;
        o0.x = fmaxf(0.25f * v[0] + b0.x, 0.f);
        o0.y = fmaxf(0.25f * v[1] + b0.y, 0.f);
        o0.z = fmaxf(0.25f * v[2] + b0.z, 0.f);
        o0.w = fmaxf(0.25f * v[3] + b0.w, 0.f);
        o1.x = fmaxf(0.25f * v[4] + b1.x, 0.f);
        o1.y = fmaxf(0.25f * v[5] + b1.y, 0.f);
        o1.z = fmaxf(0.25f * v[6] + b1.z, 0.f);
        o1.w = fmaxf(0.25f * v[7] + b1.w, 0.f);
        float* outp = writeOut ? dout : g_h;
        ((float4*)(outp + n * DD))[lane * 2]     = o0;
        ((float4*)(outp + n * DD))[lane * 2 + 1] = o1;
    }
}

// ---------------- launch ----------------
extern "C" void kernel_launch(void* const* d_in, const int* in_sizes, int n_in,
                              void* d_out, int out_size) {
    const float* x   = (const float*)d_in[0];
    const float* ea  = (const float*)d_in[1];
    const int*   ei  = (const int*)  d_in[2];
    const float* fW  = (const float*)d_in[3];
    const float* fb  = (const float*)d_in[4];
    const float* feW = (const float*)d_in[5];
    const float* feb = (const float*)d_in[6];
    const float* Wl  = (const float*)d_in[7];
    const float* bl  = (const float*)d_in[8];
    const float* Wr  = (const float*)d_in[9];
    const float* br  = (const float*)d_in[10];
    const float* We  = (const float*)d_in[11];
    const float* att = (const float*)d_in[12];
    const float* bias= (const float*)d_in[13];

    // prologue
    k_h0<<<NN / 4, 256>>>(x, fW, fb);
    k_zero<<<(NN + 255) / 256, 256>>>();
    k_hist<<<(NE + 255) / 256, 256>>>(ei);
    k_scan_a<<<NSB, 256>>>();
    k_scan_b<<<1, 256>>>();
    k_scan_c<<<NSB, 256>>>();
    k_scatter<<<(NE + 255) / 256, 256>>>(ei);
    k_eemb_csr<<<(NE + 255) / 256, 256>>>(ea, feW, feb);
    k_ee<<<NE / 32, dim3(32, 8)>>>(We);

    for (int l = 0; l < 3; l++) {
        k_lin<<<dim3((NN + 31) / 32, 4), dim3(32, 8)>>>(Wl, bl, Wr, br);
        k_fused<<<(NN + 7) / 8, 256>>>(att, bias, (float*)d_out, l == 2 ? 1 : 0);
    }
}

// round 4
// speedup vs baseline: 2.6434x; 1.2644x over previous
#include <cuda_runtime.h>
#include <cuda_fp16.h>
#include <math_constants.h>

#define NN 50000
#define NE 800000
#define FIN 128
#define DD 64
#define HH 4
#define HD 256   // H*D
#define EDIM 20

#define SCHUNK 200
#define NSB 250   // NSB * SCHUNK == NN

// ---------------- scratch (device globals) ----------------
__device__ float  g_h[NN * DD];          // 12.8 MB node features
__device__ float  g_xl[NN * HD];         // 51.2 MB
__device__ float  g_xr[NN * HD];         // 51.2 MB
__device__ __half g_eecsr[NE * HD];      // 410 MB ee = e@We (CSR order, fp16)
__device__ int    g_cnt[NN];
__device__ int    g_cur[NN];
__device__ int    g_rowptr[NN + 1];
__device__ int    g_bsum[NSB];
__device__ int    g_csr_src[NE];
__device__ int    g_csr_eid[NE];

// ---------------- h0 = relu(x @ f_W + f_b) ----------------
__global__ void k_h0(const float* __restrict__ x, const float* __restrict__ fW,
                     const float* __restrict__ fb) {
    __shared__ float Ws[FIN * DD];
    __shared__ float xs[4][FIN];
    int t = threadIdx.x;
    for (int i = t; i < FIN * DD; i += 256) Ws[i] = fW[i];
    int n0 = blockIdx.x * 4;
    for (int i = t; i < 4 * FIN; i += 256) {
        int r = i / FIN, k = i % FIN;
        int n = n0 + r;
        xs[r][k] = (n < NN) ? x[n * FIN + k] : 0.f;
    }
    __syncthreads();
    int r = t >> 6, d = t & 63;
    int n = n0 + r;
    if (n < NN) {
        float acc = fb[d];
#pragma unroll 8
        for (int k = 0; k < FIN; k++) acc = fmaf(xs[r][k], Ws[k * DD + d], acc);
        g_h[n * DD + d] = fmaxf(acc, 0.f);
    }
}

// ---------------- CSR build ----------------
__global__ void k_zero() {
    int i = blockIdx.x * blockDim.x + threadIdx.x;
    if (i < NN) { g_cnt[i] = 0; g_cur[i] = 0; }
}

__global__ void k_hist(const int* __restrict__ ei) {
    int e = blockIdx.x * blockDim.x + threadIdx.x;
    if (e < NE) atomicAdd(&g_cnt[ei[NE + e]], 1);
}

__global__ void k_scan_a() {
    __shared__ int s[256];
    int b = blockIdx.x, t = threadIdx.x;
    s[t] = (t < SCHUNK) ? g_cnt[b * SCHUNK + t] : 0;
    __syncthreads();
    for (int off = 128; off; off >>= 1) {
        if (t < off) s[t] += s[t + off];
        __syncthreads();
    }
    if (t == 0) g_bsum[b] = s[0];
}

__global__ void k_scan_b() {
    __shared__ int s[NSB];
    int t = threadIdx.x;
    for (int i = t; i < NSB; i += blockDim.x) s[i] = g_bsum[i];
    __syncthreads();
    if (t == 0) {
        int run = 0;
        for (int i = 0; i < NSB; i++) { int v = s[i]; g_bsum[i] = run; run += v; }
        g_rowptr[NN] = NE;
    }
}

__global__ void k_scan_c() {
    __shared__ int s[256];
    __shared__ int cnt_s[256];
    int b = blockIdx.x, t = threadIdx.x;
    int c = (t < SCHUNK) ? g_cnt[b * SCHUNK + t] : 0;
    cnt_s[t] = c;
    s[t] = c;
    __syncthreads();
    for (int off = 1; off < 256; off <<= 1) {
        int v = (t >= off) ? s[t - off] : 0;
        __syncthreads();
        s[t] += v;
        __syncthreads();
    }
    if (t < SCHUNK) {
        int base = g_bsum[b];
        g_rowptr[b * SCHUNK + t] = base + s[t] - cnt_s[t];  // exclusive
    }
}

__global__ void k_scatter(const int* __restrict__ ei) {
    int e = blockIdx.x * blockDim.x + threadIdx.x;
    if (e >= NE) return;
    int dst = ei[NE + e];
    int pos = g_rowptr[dst] + atomicAdd(&g_cur[dst], 1);
    g_csr_src[pos] = ei[e];
    g_csr_eid[pos] = e;
}

// ---------------- ee = relu(edge_attr@feW+feb) @ We (fused, CSR order, fp16 out)
// block (32,8): lane -> 8 cols, ty -> 4 edges. 32 edges x 256 cols per block.
__global__ void k_ee(const float* __restrict__ ea, const float* __restrict__ feW,
                     const float* __restrict__ feb, const float* __restrict__ We) {
    __shared__ float4 Ws4[EDIM][64];      // 20 KB: We[k][j]
    __shared__ float  es[32][EDIM + 1];   // edge embeddings for this tile
    __shared__ float  eas[32][2];
    int t = threadIdx.y * 32 + threadIdx.x;
    for (int i = t; i < EDIM * 64; i += 256)
        Ws4[i / 64][i % 64] = ((const float4*)We)[i];
    int e0 = blockIdx.x * 32;
    if (t < 32) {
        int eid = g_csr_eid[e0 + t];
        eas[t][0] = __ldg(&ea[eid * 2]);
        eas[t][1] = __ldg(&ea[eid * 2 + 1]);
    }
    __syncthreads();
    for (int i = t; i < 32 * EDIM; i += 256) {
        int r = i / EDIM, k = i % EDIM;
        float v = fmaf(eas[r][0], __ldg(&feW[k]),
                  fmaf(eas[r][1], __ldg(&feW[EDIM + k]), __ldg(&feb[k])));
        es[r][k] = fmaxf(v, 0.f);
    }
    __syncthreads();
    int lane = threadIdx.x, ty = threadIdx.y;
    float4 a0[4], a1[4];
#pragma unroll
    for (int r = 0; r < 4; r++) { a0[r] = make_float4(0,0,0,0); a1[r] = make_float4(0,0,0,0); }
#pragma unroll
    for (int k = 0; k < EDIM; k++) {
        float4 w0 = Ws4[k][lane * 2];
        float4 w1 = Ws4[k][lane * 2 + 1];
#pragma unroll
        for (int r = 0; r < 4; r++) {
            float ev = es[ty * 4 + r][k];
            a0[r].x = fmaf(ev, w0.x, a0[r].x); a0[r].y = fmaf(ev, w0.y, a0[r].y);
            a0[r].z = fmaf(ev, w0.z, a0[r].z); a0[r].w = fmaf(ev, w0.w, a0[r].w);
            a1[r].x = fmaf(ev, w1.x, a1[r].x); a1[r].y = fmaf(ev, w1.y, a1[r].y);
            a1[r].z = fmaf(ev, w1.z, a1[r].z); a1[r].w = fmaf(ev, w1.w, a1[r].w);
        }
    }
#pragma unroll
    for (int r = 0; r < 4; r++) {
        int e = e0 + ty * 4 + r;
        __half2 h0 = __floats2half2_rn(a0[r].x, a0[r].y);
        __half2 h1 = __floats2half2_rn(a0[r].z, a0[r].w);
        __half2 h2 = __floats2half2_rn(a1[r].x, a1[r].y);
        __half2 h3 = __floats2half2_rn(a1[r].z, a1[r].w);
        uint4 u;
        u.x = *(unsigned int*)&h0; u.y = *(unsigned int*)&h1;
        u.z = *(unsigned int*)&h2; u.w = *(unsigned int*)&h3;
        ((uint4*)(g_eecsr + (size_t)e * HD))[lane] = u;
    }
}

// ---------------- xl = h@Wl+bl, xr = h@Wr+br ----------------
__global__ void k_lin(const float* __restrict__ Wl, const float* __restrict__ bl,
                      const float* __restrict__ Wr, const float* __restrict__ br) {
    __shared__ float4 Ws[DD][32];
    __shared__ float  hs[32][DD];
    int t = threadIdx.y * 32 + threadIdx.x;
    int tile_c = blockIdx.y * 128;
    const float* W  = (tile_c < HD) ? Wl : Wr;
    const float* bb = (tile_c < HD) ? bl : br;
    int cb = tile_c & (HD - 1);
    for (int i = t; i < DD * 32; i += 256) {
        int k = i / 32, q = i % 32;
        Ws[k][q] = ((const float4*)(W + k * HD + cb))[q];
    }
    int n0 = blockIdx.x * 32;
    for (int i = t; i < 32 * DD; i += 256) {
        int r = i / DD, k = i % DD;
        int n = n0 + r;
        hs[r][k] = (n < NN) ? g_h[n * DD + k] : 0.f;
    }
    __syncthreads();
    int lane = threadIdx.x, ty = threadIdx.y;
    float4 bv = ((const float4*)(bb + cb))[lane];
    float4 acc[4];
#pragma unroll
    for (int q = 0; q < 4; q++) acc[q] = bv;
#pragma unroll 16
    for (int k = 0; k < DD; k++) {
        float4 w = Ws[k][lane];
#pragma unroll
        for (int q = 0; q < 4; q++) {
            float hv = hs[ty * 4 + q][k];
            acc[q].x = fmaf(hv, w.x, acc[q].x);
            acc[q].y = fmaf(hv, w.y, acc[q].y);
            acc[q].z = fmaf(hv, w.z, acc[q].z);
            acc[q].w = fmaf(hv, w.w, acc[q].w);
        }
    }
    float* outp = (tile_c < HD) ? g_xl : g_xr;
#pragma unroll
    for (int q = 0; q < 4; q++) {
        int n = n0 + ty * 4 + q;
        if (n < NN) ((float4*)(outp + n * HD + cb))[lane] = acc[q];
    }
}

// ---------------- fused: score + online softmax + aggregate + head-mean ------
// one warp per dst node; lane handles dims j = lane*8 .. lane*8+7 (head = lane>>3)
__global__ void __launch_bounds__(256) k_fused(const float* __restrict__ att,
                        const float* __restrict__ bias, float* __restrict__ dout,
                        int writeOut) {
    int t = threadIdx.x;
    int wid = t >> 5, lane = t & 31;
    int n = blockIdx.x * 8 + wid;
    if (n >= NN) return;

    int beg = g_rowptr[n], end = g_rowptr[n + 1];

    const float4* xr4 = (const float4*)(g_xr + (size_t)n * HD);
    float4 r0 = xr4[lane * 2], r1 = xr4[lane * 2 + 1];
    float4 av0 = __ldg(&((const float4*)att)[lane * 2]);
    float4 av1 = __ldg(&((const float4*)att)[lane * 2 + 1]);

    float m_run = -CUDART_INF_F, s_run = 0.f;
    float4 acc0 = make_float4(0, 0, 0, 0), acc1 = make_float4(0, 0, 0, 0);

    // software pipelined (depth 1)
    float4 a, b;
    uint4  u;
    if (beg < end) {
        int src = __ldg(&g_csr_src[beg]);
        const float4* xl4 = (const float4*)(g_xl + (size_t)src * HD);
        a = __ldg(&xl4[lane * 2]);
        b = __ldg(&xl4[lane * 2 + 1]);
        u = __ldcs(&((const uint4*)(g_eecsr + (size_t)beg * HD))[lane]);
    }

    for (int p = beg; p < end; p++) {
        float4 ca = a, cb = b;
        uint4  cu = u;
        if (p + 1 < end) {
            int src = __ldg(&g_csr_src[p + 1]);
            const float4* xl4 = (const float4*)(g_xl + (size_t)src * HD);
            a = __ldg(&xl4[lane * 2]);
            b = __ldg(&xl4[lane * 2 + 1]);
            u = __ldcs(&((const uint4*)(g_eecsr + (size_t)(p + 1) * HD))[lane]);
        }
        float2 p0 = __half22float2(*(__half2*)&cu.x);
        float2 p1 = __half22float2(*(__half2*)&cu.y);
        float2 p2 = __half22float2(*(__half2*)&cu.z);
        float2 p3 = __half22float2(*(__half2*)&cu.w);

        // leaky_relu(xl + xr + ee) dot att
        float s = 0.f;
        {
            float m;
            m = ca.x + r0.x + p0.x; m = m > 0.f ? m : 0.2f * m; s = fmaf(av0.x, m, s);
            m = ca.y + r0.y + p0.y; m = m > 0.f ? m : 0.2f * m; s = fmaf(av0.y, m, s);
            m = ca.z + r0.z + p1.x; m = m > 0.f ? m : 0.2f * m; s = fmaf(av0.z, m, s);
            m = ca.w + r0.w + p1.y; m = m > 0.f ? m : 0.2f * m; s = fmaf(av0.w, m, s);
            m = cb.x + r1.x + p2.x; m = m > 0.f ? m : 0.2f * m; s = fmaf(av1.x, m, s);
            m = cb.y + r1.y + p2.y; m = m > 0.f ? m : 0.2f * m; s = fmaf(av1.y, m, s);
            m = cb.z + r1.z + p3.x; m = m > 0.f ? m : 0.2f * m; s = fmaf(av1.z, m, s);
            m = cb.w + r1.w + p3.y; m = m > 0.f ? m : 0.2f * m; s = fmaf(av1.w, m, s);
        }
        // reduce within the 8-lane head group
        s += __shfl_xor_sync(0xffffffffu, s, 1);
        s += __shfl_xor_sync(0xffffffffu, s, 2);
        s += __shfl_xor_sync(0xffffffffu, s, 4);

        // online softmax update (replicated across the 8 lanes of the head)
        float nm   = fmaxf(m_run, s);
        float corr = __expf(m_run - nm);
        float w    = __expf(s - nm);
        m_run = nm;
        s_run = fmaf(s_run, corr, w);
        acc0.x = fmaf(acc0.x, corr, w * ca.x); acc0.y = fmaf(acc0.y, corr, w * ca.y);
        acc0.z = fmaf(acc0.z, corr, w * ca.z); acc0.w = fmaf(acc0.w, corr, w * ca.w);
        acc1.x = fmaf(acc1.x, corr, w * cb.x); acc1.y = fmaf(acc1.y, corr, w * cb.y);
        acc1.z = fmaf(acc1.z, corr, w * cb.z); acc1.w = fmaf(acc1.w, corr, w * cb.w);
    }

    float inv = (end > beg) ? 1.f / s_run : 0.f;
    float v[8];
    v[0] = acc0.x * inv; v[1] = acc0.y * inv; v[2] = acc0.z * inv; v[3] = acc0.w * inv;
    v[4] = acc1.x * inv; v[5] = acc1.y * inv; v[6] = acc1.z * inv; v[7] = acc1.w * inv;
    // head-mean butterfly (head index = lane bits 3,4)
#pragma unroll
    for (int u2 = 0; u2 < 8; u2++) {
        v[u2] += __shfl_xor_sync(0xffffffffu, v[u2], 8);
        v[u2] += __shfl_xor_sync(0xffffffffu, v[u2], 16);
    }
    if (lane < 8) {
        float4 b0 = __ldg(&((const float4*)bias)[lane * 2]);
        float4 b1 = __ldg(&((const float4*)bias)[lane * 2 + 1]);
        float4 o0, o1;
        o0.x = fmaxf(0.25f * v[0] + b0.x, 0.f);
        o0.y = fmaxf(0.25f * v[1] + b0.y, 0.f);
        o0.z = fmaxf(0.25f * v[2] + b0.z, 0.f);
        o0.w = fmaxf(0.25f * v[3] + b0.w, 0.f);
        o1.x = fmaxf(0.25f * v[4] + b1.x, 0.f);
        o1.y = fmaxf(0.25f * v[5] + b1.y, 0.f);
        o1.z = fmaxf(0.25f * v[6] + b1.z, 0.f);
        o1.w = fmaxf(0.25f * v[7] + b1.w, 0.f);
        float* outp = writeOut ? dout : g_h;
        ((float4*)(outp + n * DD))[lane * 2]     = o0;
        ((float4*)(outp + n * DD))[lane * 2 + 1] = o1;
    }
}

// ---------------- launch ----------------
extern "C" void kernel_launch(void* const* d_in, const int* in_sizes, int n_in,
                              void* d_out, int out_size) {
    const float* x   = (const float*)d_in[0];
    const float* ea  = (const float*)d_in[1];
    const int*   ei  = (const int*)  d_in[2];
    const float* fW  = (const float*)d_in[3];
    const float* fb  = (const float*)d_in[4];
    const float* feW = (const float*)d_in[5];
    const float* feb = (const float*)d_in[6];
    const float* Wl  = (const float*)d_in[7];
    const float* bl  = (const float*)d_in[8];
    const float* Wr  = (const float*)d_in[9];
    const float* br  = (const float*)d_in[10];
    const float* We  = (const float*)d_in[11];
    const float* att = (const float*)d_in[12];
    const float* bias= (const float*)d_in[13];

    // prologue
    k_h0<<<NN / 4, 256>>>(x, fW, fb);
    k_zero<<<(NN + 255) / 256, 256>>>();
    k_hist<<<(NE + 255) / 256, 256>>>(ei);
    k_scan_a<<<NSB, 256>>>();
    k_scan_b<<<1, 256>>>();
    k_scan_c<<<NSB, 256>>>();
    k_scatter<<<(NE + 255) / 256, 256>>>(ei);
    k_ee<<<NE / 32, dim3(32, 8)>>>(ea, feW, feb, We);

    for (int l = 0; l < 3; l++) {
        k_lin<<<dim3((NN + 31) / 32, 4), dim3(32, 8)>>>(Wl, bl, Wr, br);
        k_fused<<<(NN + 7) / 8, 256>>>(att, bias, (float*)d_out, l == 2 ? 1 : 0);
    }
}

// round 5
// speedup vs baseline: 2.6923x; 1.0185x over previous
#include <cuda_runtime.h>
#include <cuda_fp16.h>
#include <math_constants.h>

#define NN 50000
#define NE 800000
#define FIN 128
#define DD 64
#define HH 4
#define HD 256   // H*D
#define EDIM 20

#define SCHUNK 200
#define NSB 250   // NSB * SCHUNK == NN

// ---------------- scratch (device globals) ----------------
__device__ float  g_h[NN * DD];          // 12.8 MB node features
__device__ __half g_xl[NN * HD];         // 25.6 MB (fp16 gather payload)
__device__ float  g_xr[NN * HD];         // 51.2 MB
__device__ __half g_eecsr[NE * HD];      // 410 MB ee = e@We (CSR order, fp16)
__device__ int    g_cnt[NN];
__device__ int    g_cur[NN];
__device__ int    g_rowptr[NN + 1];
__device__ int    g_bsum[NSB];
__device__ int    g_csr_src[NE];
__device__ int    g_csr_eid[NE];

// ---------------- h0 = relu(x @ f_W + f_b) ----------------
__global__ void k_h0(const float* __restrict__ x, const float* __restrict__ fW,
                     const float* __restrict__ fb) {
    __shared__ float Ws[FIN * DD];
    __shared__ float xs[4][FIN];
    int t = threadIdx.x;
    for (int i = t; i < FIN * DD; i += 256) Ws[i] = fW[i];
    int n0 = blockIdx.x * 4;
    for (int i = t; i < 4 * FIN; i += 256) {
        int r = i / FIN, k = i % FIN;
        int n = n0 + r;
        xs[r][k] = (n < NN) ? x[n * FIN + k] : 0.f;
    }
    __syncthreads();
    int r = t >> 6, d = t & 63;
    int n = n0 + r;
    if (n < NN) {
        float acc = fb[d];
#pragma unroll 8
        for (int k = 0; k < FIN; k++) acc = fmaf(xs[r][k], Ws[k * DD + d], acc);
        g_h[n * DD + d] = fmaxf(acc, 0.f);
    }
}

// ---------------- CSR build ----------------
__global__ void k_zero() {
    int i = blockIdx.x * blockDim.x + threadIdx.x;
    if (i < NN) { g_cnt[i] = 0; g_cur[i] = 0; }
}

__global__ void k_hist(const int* __restrict__ ei) {
    int e = blockIdx.x * blockDim.x + threadIdx.x;
    if (e < NE) atomicAdd(&g_cnt[ei[NE + e]], 1);
}

__global__ void k_scan_a() {
    __shared__ int s[256];
    int b = blockIdx.x, t = threadIdx.x;
    s[t] = (t < SCHUNK) ? g_cnt[b * SCHUNK + t] : 0;
    __syncthreads();
    for (int off = 128; off; off >>= 1) {
        if (t < off) s[t] += s[t + off];
        __syncthreads();
    }
    if (t == 0) g_bsum[b] = s[0];
}

__global__ void k_scan_b() {
    __shared__ int s[NSB];
    int t = threadIdx.x;
    for (int i = t; i < NSB; i += blockDim.x) s[i] = g_bsum[i];
    __syncthreads();
    if (t == 0) {
        int run = 0;
        for (int i = 0; i < NSB; i++) { int v = s[i]; g_bsum[i] = run; run += v; }
        g_rowptr[NN] = NE;
    }
}

__global__ void k_scan_c() {
    __shared__ int s[256];
    __shared__ int cnt_s[256];
    int b = blockIdx.x, t = threadIdx.x;
    int c = (t < SCHUNK) ? g_cnt[b * SCHUNK + t] : 0;
    cnt_s[t] = c;
    s[t] = c;
    __syncthreads();
    for (int off = 1; off < 256; off <<= 1) {
        int v = (t >= off) ? s[t - off] : 0;
        __syncthreads();
        s[t] += v;
        __syncthreads();
    }
    if (t < SCHUNK) {
        int base = g_bsum[b];
        g_rowptr[b * SCHUNK + t] = base + s[t] - cnt_s[t];  // exclusive
    }
}

__global__ void k_scatter(const int* __restrict__ ei) {
    int e = blockIdx.x * blockDim.x + threadIdx.x;
    if (e >= NE) return;
    int dst = ei[NE + e];
    int pos = g_rowptr[dst] + atomicAdd(&g_cur[dst], 1);
    g_csr_src[pos] = ei[e];
    g_csr_eid[pos] = e;
}

// ---------------- ee = relu(edge_attr@feW+feb) @ We (fused, CSR order, fp16 out)
__global__ void k_ee(const float* __restrict__ ea, const float* __restrict__ feW,
                     const float* __restrict__ feb, const float* __restrict__ We) {
    __shared__ float4 Ws4[EDIM][64];
    __shared__ float  es[32][EDIM + 1];
    __shared__ float  eas[32][2];
    int t = threadIdx.y * 32 + threadIdx.x;
    for (int i = t; i < EDIM * 64; i += 256)
        Ws4[i / 64][i % 64] = ((const float4*)We)[i];
    int e0 = blockIdx.x * 32;
    if (t < 32) {
        int eid = g_csr_eid[e0 + t];
        eas[t][0] = __ldg(&ea[eid * 2]);
        eas[t][1] = __ldg(&ea[eid * 2 + 1]);
    }
    __syncthreads();
    for (int i = t; i < 32 * EDIM; i += 256) {
        int r = i / EDIM, k = i % EDIM;
        float v = fmaf(eas[r][0], __ldg(&feW[k]),
                  fmaf(eas[r][1], __ldg(&feW[EDIM + k]), __ldg(&feb[k])));
        es[r][k] = fmaxf(v, 0.f);
    }
    __syncthreads();
    int lane = threadIdx.x, ty = threadIdx.y;
    float4 a0[4], a1[4];
#pragma unroll
    for (int r = 0; r < 4; r++) { a0[r] = make_float4(0,0,0,0); a1[r] = make_float4(0,0,0,0); }
#pragma unroll
    for (int k = 0; k < EDIM; k++) {
        float4 w0 = Ws4[k][lane * 2];
        float4 w1 = Ws4[k][lane * 2 + 1];
#pragma unroll
        for (int r = 0; r < 4; r++) {
            float ev = es[ty * 4 + r][k];
            a0[r].x = fmaf(ev, w0.x, a0[r].x); a0[r].y = fmaf(ev, w0.y, a0[r].y);
            a0[r].z = fmaf(ev, w0.z, a0[r].z); a0[r].w = fmaf(ev, w0.w, a0[r].w);
            a1[r].x = fmaf(ev, w1.x, a1[r].x); a1[r].y = fmaf(ev, w1.y, a1[r].y);
            a1[r].z = fmaf(ev, w1.z, a1[r].z); a1[r].w = fmaf(ev, w1.w, a1[r].w);
        }
    }
#pragma unroll
    for (int r = 0; r < 4; r++) {
        int e = e0 + ty * 4 + r;
        __half2 h0 = __floats2half2_rn(a0[r].x, a0[r].y);
        __half2 h1 = __floats2half2_rn(a0[r].z, a0[r].w);
        __half2 h2 = __floats2half2_rn(a1[r].x, a1[r].y);
        __half2 h3 = __floats2half2_rn(a1[r].z, a1[r].w);
        uint4 u;
        u.x = *(unsigned int*)&h0; u.y = *(unsigned int*)&h1;
        u.z = *(unsigned int*)&h2; u.w = *(unsigned int*)&h3;
        ((uint4*)(g_eecsr + (size_t)e * HD))[lane] = u;
    }
}

// ---------------- xl(fp16) = h@Wl+bl, xr(fp32) = h@Wr+br ----------------
__global__ void k_lin(const float* __restrict__ Wl, const float* __restrict__ bl,
                      const float* __restrict__ Wr, const float* __restrict__ br) {
    __shared__ float4 Ws[DD][32];
    __shared__ float  hs[32][DD];
    int t = threadIdx.y * 32 + threadIdx.x;
    int tile_c = blockIdx.y * 128;
    int isL = (tile_c < HD);
    const float* W  = isL ? Wl : Wr;
    const float* bb = isL ? bl : br;
    int cb = tile_c & (HD - 1);
    for (int i = t; i < DD * 32; i += 256) {
        int k = i / 32, q = i % 32;
        Ws[k][q] = ((const float4*)(W + k * HD + cb))[q];
    }
    int n0 = blockIdx.x * 32;
    for (int i = t; i < 32 * DD; i += 256) {
        int r = i / DD, k = i % DD;
        int n = n0 + r;
        hs[r][k] = (n < NN) ? g_h[n * DD + k] : 0.f;
    }
    __syncthreads();
    int lane = threadIdx.x, ty = threadIdx.y;
    float4 bv = ((const float4*)(bb + cb))[lane];
    float4 acc[4];
#pragma unroll
    for (int q = 0; q < 4; q++) acc[q] = bv;
#pragma unroll 16
    for (int k = 0; k < DD; k++) {
        float4 w = Ws[k][lane];
#pragma unroll
        for (int q = 0; q < 4; q++) {
            float hv = hs[ty * 4 + q][k];
            acc[q].x = fmaf(hv, w.x, acc[q].x);
            acc[q].y = fmaf(hv, w.y, acc[q].y);
            acc[q].z = fmaf(hv, w.z, acc[q].z);
            acc[q].w = fmaf(hv, w.w, acc[q].w);
        }
    }
    if (isL) {
#pragma unroll
        for (int q = 0; q < 4; q++) {
            int n = n0 + ty * 4 + q;
            if (n < NN) {
                __half2 h0 = __floats2half2_rn(acc[q].x, acc[q].y);
                __half2 h1 = __floats2half2_rn(acc[q].z, acc[q].w);
                uint2 u;
                u.x = *(unsigned int*)&h0; u.y = *(unsigned int*)&h1;
                *((uint2*)(g_xl + (size_t)n * HD + cb) + lane) = u;
            }
        }
    } else {
#pragma unroll
        for (int q = 0; q < 4; q++) {
            int n = n0 + ty * 4 + q;
            if (n < NN) ((float4*)(g_xr + (size_t)n * HD + cb))[lane] = acc[q];
        }
    }
}

// ---------------- fused: score + online softmax + aggregate + head-mean ------
// one warp per dst node; lane handles dims j = lane*8 .. lane*8+7 (head = lane>>3)
__global__ void __launch_bounds__(256) k_fused(const float* __restrict__ att,
                        const float* __restrict__ bias, float* __restrict__ dout,
                        int writeOut) {
    int t = threadIdx.x;
    int wid = t >> 5, lane = t & 31;
    int n = blockIdx.x * 8 + wid;
    if (n >= NN) return;

    int beg = g_rowptr[n], end = g_rowptr[n + 1];

    const float4* xr4 = (const float4*)(g_xr + (size_t)n * HD);
    float4 r0 = xr4[lane * 2], r1 = xr4[lane * 2 + 1];
    float4 av0 = __ldg(&((const float4*)att)[lane * 2]);
    float4 av1 = __ldg(&((const float4*)att)[lane * 2 + 1]);

    float m_run = -CUDART_INF_F, s_run = 0.f;
    float4 acc0 = make_float4(0, 0, 0, 0), acc1 = make_float4(0, 0, 0, 0);

    // depth-2 software pipeline
    uint4 xa0, ea0, xa1, ea1;
    if (beg < end) {
        int src = __ldg(&g_csr_src[beg]);
        xa0 = __ldg(&((const uint4*)(g_xl + (size_t)src * HD))[lane]);
        ea0 = __ldcs(&((const uint4*)(g_eecsr + (size_t)beg * HD))[lane]);
    }
    if (beg + 1 < end) {
        int src = __ldg(&g_csr_src[beg + 1]);
        xa1 = __ldg(&((const uint4*)(g_xl + (size_t)src * HD))[lane]);
        ea1 = __ldcs(&((const uint4*)(g_eecsr + (size_t)(beg + 1) * HD))[lane]);
    }

#define PROCESS(XU, EU)                                                           \
    {                                                                             \
        float2 x0 = __half22float2(*(__half2*)&(XU).x);                           \
        float2 x1 = __half22float2(*(__half2*)&(XU).y);                           \
        float2 x2 = __half22float2(*(__half2*)&(XU).z);                           \
        float2 x3 = __half22float2(*(__half2*)&(XU).w);                           \
        float2 q0 = __half22float2(*(__half2*)&(EU).x);                           \
        float2 q1 = __half22float2(*(__half2*)&(EU).y);                           \
        float2 q2 = __half22float2(*(__half2*)&(EU).z);                           \
        float2 q3 = __half22float2(*(__half2*)&(EU).w);                           \
        float s = 0.f, m;                                                         \
        m = x0.x + r0.x + q0.x; m = m > 0.f ? m : 0.2f * m; s = fmaf(av0.x, m, s);\
        m = x0.y + r0.y + q0.y; m = m > 0.f ? m : 0.2f * m; s = fmaf(av0.y, m, s);\
        m = x1.x + r0.z + q1.x; m = m > 0.f ? m : 0.2f * m; s = fmaf(av0.z, m, s);\
        m = x1.y + r0.w + q1.y; m = m > 0.f ? m : 0.2f * m; s = fmaf(av0.w, m, s);\
        m = x2.x + r1.x + q2.x; m = m > 0.f ? m : 0.2f * m; s = fmaf(av1.x, m, s);\
        m = x2.y + r1.y + q2.y; m = m > 0.f ? m : 0.2f * m; s = fmaf(av1.y, m, s);\
        m = x3.x + r1.z + q3.x; m = m > 0.f ? m : 0.2f * m; s = fmaf(av1.z, m, s);\
        m = x3.y + r1.w + q3.y; m = m > 0.f ? m : 0.2f * m; s = fmaf(av1.w, m, s);\
        s += __shfl_xor_sync(0xffffffffu, s, 1);                                  \
        s += __shfl_xor_sync(0xffffffffu, s, 2);                                  \
        s += __shfl_xor_sync(0xffffffffu, s, 4);                                  \
        float nm   = fmaxf(m_run, s);                                             \
        float corr = __expf(m_run - nm);                                          \
        float w    = __expf(s - nm);                                              \
        m_run = nm;                                                               \
        s_run = fmaf(s_run, corr, w);                                             \
        acc0.x = fmaf(acc0.x, corr, w * x0.x); acc0.y = fmaf(acc0.y, corr, w * x0.y); \
        acc0.z = fmaf(acc0.z, corr, w * x1.x); acc0.w = fmaf(acc0.w, corr, w * x1.y); \
        acc1.x = fmaf(acc1.x, corr, w * x2.x); acc1.y = fmaf(acc1.y, corr, w * x2.y); \
        acc1.z = fmaf(acc1.z, corr, w * x3.x); acc1.w = fmaf(acc1.w, corr, w * x3.y); \
    }

    for (int p = beg; p < end; p += 2) {
        PROCESS(xa0, ea0);
        if (p + 2 < end) {
            int src = __ldg(&g_csr_src[p + 2]);
            xa0 = __ldg(&((const uint4*)(g_xl + (size_t)src * HD))[lane]);
            ea0 = __ldcs(&((const uint4*)(g_eecsr + (size_t)(p + 2) * HD))[lane]);
        }
        if (p + 1 < end) {
            PROCESS(xa1, ea1);
            if (p + 3 < end) {
                int src = __ldg(&g_csr_src[p + 3]);
                xa1 = __ldg(&((const uint4*)(g_xl + (size_t)src * HD))[lane]);
                ea1 = __ldcs(&((const uint4*)(g_eecsr + (size_t)(p + 3) * HD))[lane]);
            }
        }
    }
#undef PROCESS

    float inv = (end > beg) ? 1.f / s_run : 0.f;
    float v[8];
    v[0] = acc0.x * inv; v[1] = acc0.y * inv; v[2] = acc0.z * inv; v[3] = acc0.w * inv;
    v[4] = acc1.x * inv; v[5] = acc1.y * inv; v[6] = acc1.z * inv; v[7] = acc1.w * inv;
#pragma unroll
    for (int u2 = 0; u2 < 8; u2++) {
        v[u2] += __shfl_xor_sync(0xffffffffu, v[u2], 8);
        v[u2] += __shfl_xor_sync(0xffffffffu, v[u2], 16);
    }
    if (lane < 8) {
        float4 b0 = __ldg(&((const float4*)bias)[lane * 2]);
        float4 b1 = __ldg(&((const float4*)bias)[lane * 2 + 1]);
        float4 o0, o1;
        o0.x = fmaxf(0.25f * v[0] + b0.x, 0.f);
        o0.y = fmaxf(0.25f * v[1] + b0.y, 0.f);
        o0.z = fmaxf(0.25f * v[2] + b0.z, 0.f);
        o0.w = fmaxf(0.25f * v[3] + b0.w, 0.f);
        o1.x = fmaxf(0.25f * v[4] + b1.x, 0.f);
        o1.y = fmaxf(0.25f * v[5] + b1.y, 0.f);
        o1.z = fmaxf(0.25f * v[6] + b1.z, 0.f);
        o1.w = fmaxf(0.25f * v[7] + b1.w, 0.f);
        float* outp = writeOut ? dout : g_h;
        ((float4*)(outp + n * DD))[lane * 2]     = o0;
        ((float4*)(outp + n * DD))[lane * 2 + 1] = o1;
    }
}

// ---------------- launch ----------------
extern "C" void kernel_launch(void* const* d_in, const int* in_sizes, int n_in,
                              void* d_out, int out_size) {
    const float* x   = (const float*)d_in[0];
    const float* ea  = (const float*)d_in[1];
    const int*   ei  = (const int*)  d_in[2];
    const float* fW  = (const float*)d_in[3];
    const float* fb  = (const float*)d_in[4];
    const float* feW = (const float*)d_in[5];
    const float* feb = (const float*)d_in[6];
    const float* Wl  = (const float*)d_in[7];
    const float* bl  = (const float*)d_in[8];
    const float* Wr  = (const float*)d_in[9];
    const float* br  = (const float*)d_in[10];
    const float* We  = (const float*)d_in[11];
    const float* att = (const float*)d_in[12];
    const float* bias= (const float*)d_in[13];

    // prologue
    k_h0<<<NN / 4, 256>>>(x, fW, fb);
    k_zero<<<(NN + 255) / 256, 256>>>();
    k_hist<<<(NE + 255) / 256, 256>>>(ei);
    k_scan_a<<<NSB, 256>>>();
    k_scan_b<<<1, 256>>>();
    k_scan_c<<<NSB, 256>>>();
    k_scatter<<<(NE + 255) / 256, 256>>>(ei);
    k_ee<<<NE / 32, dim3(32, 8)>>>(ea, feW, feb, We);

    for (int l = 0; l < 3; l++) {
        k_lin<<<dim3((NN + 31) / 32, 4), dim3(32, 8)>>>(Wl, bl, Wr, br);
        k_fused<<<(NN + 7) / 8, 256>>>(att, bias, (float*)d_out, l == 2 ? 1 : 0);
    }
}